// round 17
// baseline (speedup 1.0000x reference)
#include <cuda_runtime.h>
#include <math_constants.h>

#define BB   4
#define NP   2048
#define KNN  64
#define EPS  0.005f
#define LOG_MU (-7.6246190f)   /* -log(2048) */
#define NBLK 256               /* iterate blocks per batch = column partials */
#define NCAND 256              /* knn candidate capacity */

/* ------------ scratch (no allocations allowed) ------------ */
__device__ float g_lv[BB*NP];
__device__ float g_sin[BB*NP];
__device__ float g_spr[BB*NP];
__device__ int   g_assign[BB*NP];
__device__ float g_avg[BB*NP];
__device__ float g_cmx[BB][NBLK][NP];   /* column partial max (per row-block) */
__device__ float g_csm[BB][NBLK][NP];   /* column partial sum                 */
/* materialized logK = -C/eps : [b][n][m] — 67 MB */
__device__ float g_K [(size_t)BB*NP*NP];

/* TF32 rounding (cuBLAS/CUTLASS conversion path: round-nearest-ties-away) */
__device__ __forceinline__ float tf32r(float x)
{
    float r;
    asm("cvt.rna.tf32.f32 %0, %1;" : "=f"(r) : "f"(x));
    return r;
}

/* online branchy logsumexp update (fast exp) */
#define ONL(e, mx, s) \
    { if ((e) > (mx)) { (s) = fmaf((s), __expf((mx) - (e)), 1.f); (mx) = (e); } \
      else              (s) += __expf((e) - (mx)); }

/* pairwise lse merge */
#define LSEMRG(mx, s, m2, s2) \
    { float _nm = fmaxf((mx), (m2)); \
      (s) = (s) * __expf((mx) - _nm) + (s2) * __expf((m2) - _nm); \
      (mx) = _nm; }

/* ------------ threefry2x32, bit-exact vs JAX ------------ */
__device__ __forceinline__ void threefry2x32(unsigned k0, unsigned k1,
                                             unsigned &x0, unsigned &x1)
{
    unsigned ks2 = k0 ^ k1 ^ 0x1BD11BDAu;
    x0 += k0; x1 += k1;
#define TFR(r) { x0 += x1; x1 = (x1 << (r)) | (x1 >> (32 - (r))); x1 ^= x0; }
    TFR(13) TFR(15) TFR(26) TFR(6)
    x0 += k1;  x1 += ks2 + 1u;
    TFR(17) TFR(29) TFR(16) TFR(24)
    x0 += ks2; x1 += k0 + 2u;
    TFR(13) TFR(15) TFR(26) TFR(6)
    x0 += k0;  x1 += k1 + 3u;
    TFR(17) TFR(29) TFR(16) TFR(24)
    x0 += k1;  x1 += ks2 + 4u;
    TFR(13) TFR(15) TFR(26) TFR(6)
    x0 += ks2; x1 += k0 + 5u;
#undef TFR
}

/* ------------ init: squared norms (full fp32) + zero lv ------------ */
__global__ void init_kernel(const float* __restrict__ preds,
                            const float* __restrict__ inputs)
{
    int i = blockIdx.x * blockDim.x + threadIdx.x;
    if (i < BB*NP) {
        float x = inputs[3*i], y = inputs[3*i+1], z = inputs[3*i+2];
        g_sin[i] = fmaf(z, z, fmaf(y, y, x*x));
        x = preds[3*i]; y = preds[3*i+1]; z = preds[3*i+2];
        g_spr[i] = fmaf(z, z, fmaf(y, y, x*x));
        g_lv[i] = 0.f;
    }
}

/* ------------ build logK: g_K[b][n][m], rows = inputs, cols = preds ------------ */
__global__ void __launch_bounds__(256) build_logK(
    const float* __restrict__ rowPts,
    const float* __restrict__ innerPts)
{
    __shared__ float4 shp[NP];
    int b = blockIdx.y;
    const float* ip = innerPts + b*NP*3;
    for (int i = threadIdx.x; i < NP; i += 256)
        shp[i] = make_float4(tf32r(ip[3*i]), tf32r(ip[3*i+1]), tf32r(ip[3*i+2]),
                             g_spr[b*NP + i]);
    __syncthreads();

    int warp = threadIdx.x >> 5, lane = threadIdx.x & 31;
    int row = blockIdx.x * 8 + warp;
    const float* rp = rowPts + (b*NP + row)*3;
    float ax = tf32r(rp[0]), ay = tf32r(rp[1]), az = tf32r(rp[2]);
    float sa = g_sin[b*NP + row];
    float* orow = g_K + ((size_t)b*NP + row) * NP;

    for (int m = lane; m < NP; m += 32) {
        float4 p = shp[m];
        float dot = fmaf(az, p.z, fmaf(ay, p.y, ax * p.x));
        float d2  = fmaxf(__fadd_rn(__fadd_rn(sa, p.w), -2.0f * dot), 0.f);
        orow[m] = -(d2 / EPS);
    }
}

/* ------------ one full Sinkhorn iteration body (reads g_K ONCE):
   grid (NBLK, BB). Each block: 8 rows, all 256 threads per row.
   Thread owns 8 fixed columns: {warp*256+lane*4 ..+3} and +128.
   Per row: row-lse -> lu[n] (block reduce), then column ONL accumulation
   with the register-held K values. Epilogue writes column partials.      */
__global__ void __launch_bounds__(256) sink_iter(void)
{
    __shared__ float shlv[NP];
    __shared__ float wmx[8], wsm[8];
    __shared__ float sh_lu;

    int b = blockIdx.y;
    int tid = threadIdx.x, warp = tid >> 5, lane = tid & 31;
    for (int i = tid; i < NP; i += 256) shlv[i] = g_lv[b*NP + i];
    __syncthreads();

    const float4* L4 = (const float4*)shlv;
    float4 lv0 = L4[warp*64 + lane];
    float4 lv1 = L4[warp*64 + 32 + lane];

    float cmx[8], csm[8];
#pragma unroll
    for (int j = 0; j < 8; j++) { cmx[j] = -CUDART_INF_F; csm[j] = 0.f; }

    int row0 = blockIdx.x * 8;
#pragma unroll 1
    for (int r = 0; r < 8; r++) {
        int row = row0 + r;
        const float4* M4 = (const float4*)(g_K + ((size_t)b*NP + row) * NP);
        float4 k0 = M4[warp*64 + lane];
        float4 k1 = M4[warp*64 + 32 + lane];

        /* row lse contribution: e = k + lv */
        float e0 = __fadd_rn(k0.x, lv0.x), e1 = __fadd_rn(k0.y, lv0.y);
        float e2 = __fadd_rn(k0.z, lv0.z), e3 = __fadd_rn(k0.w, lv0.w);
        float e4 = __fadd_rn(k1.x, lv1.x), e5 = __fadd_rn(k1.y, lv1.y);
        float e6 = __fadd_rn(k1.z, lv1.z), e7 = __fadd_rn(k1.w, lv1.w);

        float tmx = fmaxf(fmaxf(fmaxf(e0, e1), fmaxf(e2, e3)),
                          fmaxf(fmaxf(e4, e5), fmaxf(e6, e7)));
        float ts = __expf(e0 - tmx) + __expf(e1 - tmx)
                 + __expf(e2 - tmx) + __expf(e3 - tmx)
                 + __expf(e4 - tmx) + __expf(e5 - tmx)
                 + __expf(e6 - tmx) + __expf(e7 - tmx);

#pragma unroll
        for (int off = 16; off; off >>= 1) {
            float om = __shfl_xor_sync(0xffffffffu, tmx, off);
            float os = __shfl_xor_sync(0xffffffffu, ts,  off);
            LSEMRG(tmx, ts, om, os)
        }
        if (lane == 0) { wmx[warp] = tmx; wsm[warp] = ts; }
        __syncthreads();
        if (tid == 0) {
            float mx = wmx[0], s = wsm[0];
#pragma unroll
            for (int w = 1; w < 8; w++) LSEMRG(mx, s, wmx[w], wsm[w])
            sh_lu = __fadd_rn(LOG_MU, -__fadd_rn(logf(s), mx));
        }
        __syncthreads();
        float lu = sh_lu;

        /* column accumulation: e' = k + lu, per-column online lse */
        float e;
        e = __fadd_rn(k0.x, lu); ONL(e, cmx[0], csm[0])
        e = __fadd_rn(k0.y, lu); ONL(e, cmx[1], csm[1])
        e = __fadd_rn(k0.z, lu); ONL(e, cmx[2], csm[2])
        e = __fadd_rn(k0.w, lu); ONL(e, cmx[3], csm[3])
        e = __fadd_rn(k1.x, lu); ONL(e, cmx[4], csm[4])
        e = __fadd_rn(k1.y, lu); ONL(e, cmx[5], csm[5])
        e = __fadd_rn(k1.z, lu); ONL(e, cmx[6], csm[6])
        e = __fadd_rn(k1.w, lu); ONL(e, cmx[7], csm[7])
    }

    /* epilogue: write this block's column partials */
    int blk = blockIdx.x;
#pragma unroll
    for (int j = 0; j < 4; j++) {
        int mA = warp*256 + lane*4 + j;
        g_cmx[b][blk][mA]       = cmx[j];
        g_csm[b][blk][mA]       = csm[j];
        g_cmx[b][blk][mA + 128] = cmx[4 + j];
        g_csm[b][blk][mA + 128] = csm[4 + j];
    }
}

/* ------------ merge NBLK column partials -> lv.
   4 threads per column (64 partials each), shuffle-merged.               */
__global__ void __launch_bounds__(256) sink_merge(void)
{
    int gid = blockIdx.x * 256 + threadIdx.x;   /* 0 .. 32767 */
    int col = gid >> 2;                          /* 0 .. 8191  */
    int q   = gid & 3;
    int b = col >> 11, m = col & (NP - 1);

    float mx = -CUDART_INF_F, s = 0.f;
    int blk0 = q * (NBLK/4);
#pragma unroll 4
    for (int i = 0; i < NBLK/4; i++) {
        float m2 = g_cmx[b][blk0 + i][m];
        float s2 = g_csm[b][blk0 + i][m];
        LSEMRG(mx, s, m2, s2)
    }
#pragma unroll
    for (int off = 1; off < 4; off <<= 1) {
        float om = __shfl_xor_sync(0xffffffffu, mx, off);
        float os = __shfl_xor_sync(0xffffffffu, s,  off);
        LSEMRG(mx, s, om, os)
    }
    if (q == 0)
        g_lv[col] = __fadd_rn(LOG_MU, -__fadd_rn(logf(s), mx));
}

/* ------------ argmax over m of g_K[n][m] + lv[m]  (lu[n] const per row) ------------ */
__global__ void __launch_bounds__(256) assign_fast(void)
{
    __shared__ float shl[NP];
    int b = blockIdx.y;
    for (int i = threadIdx.x; i < NP; i += 256) shl[i] = g_lv[b*NP + i];
    __syncthreads();

    int warp = threadIdx.x >> 5, lane = threadIdx.x & 31;
    int row = blockIdx.x * 8 + warp;
    const float4* M4 = (const float4*)(g_K + ((size_t)b*NP + row) * NP);
    const float4* L4 = (const float4*)shl;

    float best = -CUDART_INF_F;
    int   bi = 0;
    for (int i = 0; i < NP/128; i++) {
        float4 k = M4[i*32 + lane];
        float4 l = L4[i*32 + lane];
        int m0 = (i*32 + lane) * 4;
        float v;
        v = __fadd_rn(k.x, l.x); if (v > best) { best = v; bi = m0;     }
        v = __fadd_rn(k.y, l.y); if (v > best) { best = v; bi = m0 + 1; }
        v = __fadd_rn(k.z, l.z); if (v > best) { best = v; bi = m0 + 2; }
        v = __fadd_rn(k.w, l.w); if (v > best) { best = v; bi = m0 + 3; }
    }
#pragma unroll
    for (int off = 16; off; off >>= 1) {
        float ov = __shfl_xor_sync(0xffffffffu, best, off);
        int   oi = __shfl_xor_sync(0xffffffffu, bi,   off);
        if (ov > best || (ov == best && oi < bi)) { best = ov; bi = oi; }
    }
    if (lane == 0) g_assign[b*NP + row] = bi;
}

/* ------------ KNN via histogram-select + small sort (bit-identical ranks) ------------ */
__global__ void __launch_bounds__(256) knn_loss_kernel(
    const float* __restrict__ inputs,
    const float* __restrict__ preds)
{
    __shared__ unsigned long long keys[NP];      /* 16 KB */
    __shared__ int counts[4096];                 /* 16 KB */
    __shared__ int scan[256];
    __shared__ unsigned long long cand[NCAND];   /* 2 KB */
    __shared__ int ccnt, sh_B;
    __shared__ float redm[KNN], redw[KNN];
    __shared__ float sh_d63;

    int row = blockIdx.x;
    int b = row >> 11, n = row & (NP - 1);
    int tid = threadIdx.x;
    const float* inp = inputs + b*NP*3;
    float ax = tf32r(inp[3*n]), ay = tf32r(inp[3*n+1]), az = tf32r(inp[3*n+2]);
    float sa = g_sin[b*NP + n];

    for (int i = tid; i < 4096; i += 256) counts[i] = 0;
    if (tid == 0) ccnt = 0;
    __syncthreads();

    for (int m = tid; m < NP; m += 256) {
        float bx = tf32r(inp[3*m]), by = tf32r(inp[3*m+1]), bz = tf32r(inp[3*m+2]);
        float dot = fmaf(az, bz, fmaf(ay, by, ax * bx));
        float d2  = fmaxf(__fadd_rn(__fadd_rn(sa, g_sin[b*NP + m]), -2.0f * dot), 0.f);
        unsigned bits = __float_as_uint(d2);
        keys[m] = (((unsigned long long)bits) << 32) | (unsigned)m;
        atomicAdd(&counts[bits >> 19], 1);
    }
    __syncthreads();

    int base = tid * 16;
    int tsum = 0;
#pragma unroll
    for (int j = 0; j < 16; j++) tsum += counts[base + j];
    scan[tid] = tsum;
    __syncthreads();
    for (int off = 1; off < 256; off <<= 1) {
        int v = (tid >= off) ? scan[tid - off] : 0;
        __syncthreads();
        scan[tid] += v;
        __syncthreads();
    }
    int incl = scan[tid];
    int exc  = incl - tsum;
    if (exc < KNN + 1 && incl >= KNN + 1) {
        int c = exc;
#pragma unroll
        for (int j = 0; j < 16; j++) {
            c += counts[base + j];
            if (c >= KNN + 1) { sh_B = base + j; break; }
        }
    }
    __syncthreads();

    int B = sh_B;
    for (int m = tid; m < NP; m += 256) {
        unsigned long long key = keys[m];
        if ((int)(key >> 51) <= B) {
            int pos = atomicAdd(&ccnt, 1);
            if (pos < NCAND) cand[pos] = key;
        }
    }
    __syncthreads();
    for (int i = ccnt + tid; i < NCAND; i += 256)
        cand[i] = 0xFFFFFFFFFFFFFFFFull;
    __syncthreads();

    for (int k = 2; k <= NCAND; k <<= 1) {
        for (int j = k >> 1; j > 0; j >>= 1) {
            int i = tid;
            int ixj = i ^ j;
            if (ixj > i && i < NCAND) {
                unsigned long long x = cand[i], y = cand[ixj];
                bool up = ((i & k) == 0);
                if ((x > y) == up) { cand[i] = y; cand[ixj] = x; }
            }
            __syncthreads();
        }
    }

    if (tid < KNN) {
        unsigned long long key = cand[tid + 1];   /* drop self (rank 0) */
        int   idx = (int)(key & 0xffffffffull);
        float d   = __uint_as_float((unsigned)(key >> 32));

        const float C1 = (float)(0.05 * 0.05);
        const float C2 = (float)(2.0 * 0.5657 * 0.5657);
        const float C3 = (float)(0.5657 * 2.5066282746);
        float prob = expf(-(d / C1) / C2) / C3;

        unsigned lin = ((unsigned)row << 6) | (unsigned)tid;
        const unsigned H = (unsigned)(BB * NP * KNN / 2);   /* 262144 */
        unsigned x0, x1, bits;
        if (lin < H) { x0 = lin;     x1 = lin + H; threefry2x32(0u, 42u, x0, x1); bits = x0; }
        else         { x0 = lin - H; x1 = lin;     threefry2x32(0u, 42u, x0, x1); bits = x1; }
        float u = __uint_as_float((bits >> 9) | 0x3f800000u) - 1.0f;
        float mask = (u < prob) ? 1.0f : 0.0f;

        int pidx = g_assign[b*NP + n];
        const float* pp = preds + (b*NP + pidx)*3;
        const float* xp = inp + idx*3;
        float dx = pp[0] - xp[0], dy = pp[1] - xp[1], dz = pp[2] - xp[2];
        float dist = fmaf(dz, dz, fmaf(dy, dy, dx * dx));

        redm[tid] = mask;
        redw[tid] = mask * dist;
        if (tid == KNN - 1) sh_d63 = dist;
    }
    __syncthreads();

    if (tid == 0) {
        float ms = 0.f, ws = 0.f;
#pragma unroll
        for (int q = 0; q < KNN; q++) { ms += redm[q]; ws += redw[q]; }
        g_avg[row] = (ms == 0.f) ? sh_d63 : (ws / ms);
    }
}

/* ------------ deterministic final reduction ------------ */
__global__ void reduce_kernel(float* __restrict__ out)
{
    __shared__ float sh[256];
    float s = 0.f;
    for (int i = threadIdx.x; i < BB*NP; i += 256) s += g_avg[i];
    sh[threadIdx.x] = s;
    __syncthreads();
    for (int off = 128; off; off >>= 1) {
        if (threadIdx.x < off) sh[threadIdx.x] += sh[threadIdx.x + off];
        __syncthreads();
    }
    if (threadIdx.x == 0) out[0] = sh[0];
}

extern "C" void kernel_launch(void* const* d_in, const int* in_sizes, int n_in,
                              void* d_out, int out_size)
{
    const float* preds  = (const float*)d_in[0];
    const float* inputs = (const float*)d_in[1];

    init_kernel<<<(BB*NP + 255) / 256, 256>>>(preds, inputs);

    dim3 g(NP / 8, BB);          /* build/assign: 256 x BB */
    dim3 gi(NBLK, BB);           /* iterate: 1024 blocks   */
    build_logK<<<g, 256>>>(inputs, preds);      /* g_K[n][m] */

    for (int it = 0; it < 50; ++it) {
        sink_iter <<<gi, 256>>>();   /* lu per row + column partials (1 K read) */
        sink_merge<<<128, 256>>>();  /* partials -> lv                          */
    }
    assign_fast<<<g, 256>>>();
    knn_loss_kernel<<<BB*NP, 256>>>(inputs, preds);
    reduce_kernel<<<1, 256>>>((float*)d_out);
}